// round 15
// baseline (speedup 1.0000x reference)
#include <cuda_runtime.h>
#include <math.h>

// ---------------------------------------------------------------------------
// Problem constants (shapes fixed by setup_inputs)
// ---------------------------------------------------------------------------
#define B_SZ   2
#define C_SZ   128
#define S_SZ   262144          // 64*64*64 voxels per (b,c)
#define NPAIR  (B_SZ * C_SZ)   // 256
#define NCHUNK 32              // fine chunks: 8192 blocks -> 98.9% wave util
#define GBASES 8               // GRID_SIZE + SPLINE_ORDER = 5 + 3

#define TILE_VOX 128                   // voxels per fused tile
#define TILE_V4  32                    // float4 lanes per tile
#define TILES_PER_B (S_SZ / TILE_VOX)  // 2048

// Scratch (no device allocation allowed)
__device__ float g_psum[NPAIR * NCHUNK];
__device__ float g_pmax[NPAIR * NCHUNK];
__device__ float g_att[NPAIR];   // sigmoid channel attention per (b,c)
__device__ float g_wc[NPAIR];    // att * conv_w  per (b,c)
__device__ float g_sink;         // prefetch sink (never actually written)

// ---------------------------------------------------------------------------
// Cox-de Boor B-spline bases, k=3, grid = arange(-3,9)*0.4 - 1  (12 knots).
// Uniform grid -> FDIV replaced by multiply with compile-time reciprocals.
// ---------------------------------------------------------------------------
__device__ __forceinline__ void bspline8(float x, float* __restrict__ out) {
    float grid[12];
#pragma unroll
    for (int i = 0; i < 12; i++) grid[i] = (float)(i - 3) * 0.4f - 1.0f;
    float b[11];
#pragma unroll
    for (int j = 0; j < 11; j++)
        b[j] = (x >= grid[j] && x < grid[j + 1]) ? 1.0f : 0.0f;
    const float inv[3] = {2.5f, 1.25f, 1.0f / 1.2f};
#pragma unroll
    for (int j = 1; j <= 3; j++) {
        const float r = inv[j - 1];
#pragma unroll
        for (int m = 0; m < 11; m++) {
            if (m < 11 - j) {
                b[m] = (x - grid[m]) * r * b[m]
                     + (grid[m + j + 1] - x) * r * b[m + 1];
            }
        }
    }
#pragma unroll
    for (int g = 0; g < GBASES; g++) out[g] = b[g];
}

__device__ __forceinline__ float siluf(float v) { return v * (1.0f / (1.0f + __expf(-v))); }
__device__ __forceinline__ float sigmoidf_(float v) { return 1.0f / (1.0f + __expf(-v)); }

// ---------------------------------------------------------------------------
// Kernel 1: per-(b,c) partial sum/max pooling.
// 8192 blocks x 256 threads, 32 KB per block, fully unrolled (8 float4 in
// flight/thread). Fine chunks fix the 2048-block version's 86.5% wave
// utilization (1.73 waves) -> 98.9% (6.92 waves).
// Block 0 pre-touches the 41 KB of MLP weights into L2 for the att kernel.
// ---------------------------------------------------------------------------
__global__ void __launch_bounds__(256) pool_kernel(
    const float* __restrict__ x,
    const float* __restrict__ ck1b, const float* __restrict__ ck1s,
    const float* __restrict__ ck2b, const float* __restrict__ ck2s,
    const float* __restrict__ convw)
{
    if (blockIdx.x == 0) {
        float acc = 0.0f;
        for (int i = threadIdx.x; i < 8192; i += 256)
            acc += __ldcg(&ck1s[i]) + __ldcg(&ck2s[i]);
        for (int i = threadIdx.x; i < 1024; i += 256)
            acc += __ldcg(&ck1b[i]) + __ldcg(&ck2b[i]);
        if (threadIdx.x < 128) acc += __ldcg(&convw[threadIdx.x]);
        if (acc == 123456789.0f) g_sink = acc;  // keep loads alive; never true
    }

    const int pair  = blockIdx.x >> 5;           // NCHUNK = 32
    const int chunk = blockIdx.x & 31;
    const float4* p = (const float4*)(x + (size_t)pair * S_SZ
                                        + (size_t)chunk * (S_SZ / NCHUNK));

    float4 v[8];
#pragma unroll
    for (int it = 0; it < 8; it++)               // (S_SZ/NCHUNK/4)/256 = 8
        v[it] = __ldcs(&p[it * 256 + threadIdx.x]);

    float s = 0.0f, m = -3.4e38f;
#pragma unroll
    for (int it = 0; it < 8; it++) {
        s += (v[it].x + v[it].y) + (v[it].z + v[it].w);
        m = fmaxf(m, fmaxf(fmaxf(v[it].x, v[it].y), fmaxf(v[it].z, v[it].w)));
    }
#pragma unroll
    for (int o = 16; o; o >>= 1) {
        s += __shfl_xor_sync(0xffffffffu, s, o);
        m = fmaxf(m, __shfl_xor_sync(0xffffffffu, m, o));
    }
    __shared__ float ss[8], sm[8];
    const int w = threadIdx.x >> 5, l = threadIdx.x & 31;
    if (l == 0) { ss[w] = s; sm[w] = m; }
    __syncthreads();
    if (threadIdx.x == 0) {
        float ts = 0.0f, tm = -3.4e38f;
#pragma unroll
        for (int i = 0; i < 8; i++) { ts += ss[i]; tm = fmaxf(tm, sm[i]); }
        g_psum[blockIdx.x] = ts;                 // blockIdx = pair*32 + chunk
        g_pmax[blockIdx.x] = tm;
    }
}

// ---------------------------------------------------------------------------
// Kernel 2: channel attention MLP — TWO blocks, one per batch (PROVEN R14).
// phase 0 now reduces 32 partials per (src,c).
// ---------------------------------------------------------------------------
__global__ void __launch_bounds__(256) att_kernel(
    const float* __restrict__ ck1b,   // [8,128]
    const float* __restrict__ ck1s,   // [8,128,8]
    const float* __restrict__ ck2b,   // [128,8]
    const float* __restrict__ ck2s,   // [128,8,8]
    const float* __restrict__ convw)  // [128]
{
    __shared__ float s_silu[256];           // [src(2)][c(128)]
    __shared__ float s_bas[256][GBASES];
    __shared__ float s_h1silu[16];          // [src][r]
    __shared__ float s_h1bas[16][GBASES];
    __shared__ float s_out[256];            // [src][c]

    const int b   = blockIdx.x;             // batch
    const int tid = threadIdx.x;

    // phase 0+1: each thread reduces one pooled value (src,c), silu + bases.
    {
        const int src = tid >> 7;            // 0 = avg, 1 = max
        const int c   = tid & 127;
        const int pair = b * C_SZ + c;
        float v;
        if (src == 0) {
            float ts = 0.0f;
#pragma unroll
            for (int k = 0; k < NCHUNK; k++) ts += g_psum[pair * NCHUNK + k];
            v = ts * (1.0f / (float)S_SZ);
        } else {
            float tm = -3.4e38f;
#pragma unroll
            for (int k = 0; k < NCHUNK; k++) tm = fmaxf(tm, g_pmax[pair * NCHUNK + k]);
            v = tm;
        }
        s_silu[tid] = siluf(v);
        bspline8(v, s_bas[tid]);
    }
    __syncthreads();

    // phase 2: layer 1 -> h1. 16 tasks (src x r) x 16 lanes (8 channels each).
    {
        const int task = tid >> 4;            // 0..15
        const int j    = tid & 15;
        const int src  = task >> 3, r = task & 7;
        const int base = src * 128;
        float acc = 0.0f;
#pragma unroll
        for (int ii = 0; ii < 8; ii++) {
            const int i = j + ii * 16;
            const int q = base + i;
            acc += s_silu[q] * ck1b[r * C_SZ + i];
            const float4* sw = (const float4*)(ck1s + (r * C_SZ + i) * GBASES);
            const float4 a0 = sw[0], a1 = sw[1];
            acc += s_bas[q][0] * a0.x + s_bas[q][1] * a0.y
                 + s_bas[q][2] * a0.z + s_bas[q][3] * a0.w
                 + s_bas[q][4] * a1.x + s_bas[q][5] * a1.y
                 + s_bas[q][6] * a1.z + s_bas[q][7] * a1.w;
        }
#pragma unroll
        for (int o = 8; o; o >>= 1) acc += __shfl_xor_sync(0xffffffffu, acc, o);
        if (j == 0) {
            const float hv = fmaxf(acc, 0.0f);
            s_h1silu[task] = siluf(hv);        // task = src*8 + r
            bspline8(hv, s_h1bas[task]);
        }
    }
    __syncthreads();

    // phase 3: layer 2 — one (src,c) output per thread.
    {
        const int src = tid >> 7, c = tid & 127;
        float acc = 0.0f;
#pragma unroll
        for (int r = 0; r < 8; r++) {
            const int hq = src * 8 + r;
            acc += s_h1silu[hq] * ck2b[c * 8 + r];
            const float4* sw = (const float4*)(ck2s + (c * 8 + r) * GBASES);
            const float4 a0 = sw[0], a1 = sw[1];
            acc += s_h1bas[hq][0] * a0.x + s_h1bas[hq][1] * a0.y
                 + s_h1bas[hq][2] * a0.z + s_h1bas[hq][3] * a0.w
                 + s_h1bas[hq][4] * a1.x + s_h1bas[hq][5] * a1.y
                 + s_h1bas[hq][6] * a1.z + s_h1bas[hq][7] * a1.w;
        }
        s_out[tid] = acc;
    }
    __syncthreads();

    // phase 4: combine avg+max, sigmoid, fold in conv_w.
    if (tid < 128) {
        const float a = sigmoidf_(s_out[tid] + s_out[128 + tid]);
        g_att[b * C_SZ + tid] = a;
        g_wc[b * C_SZ + tid]  = a * convw[tid];
    }
}

// ---------------------------------------------------------------------------
// Kernel 3: fused spatial pass — WARP-CONTIGUOUS 512B segments (PROVEN:
// ~79us, mixed R/W roofline). Tile = 128 voxels x 128 channels. 512 threads
// = 16 warps: warp w owns channels [8w, 8w+8), lane l = float4 lane.
// Register tile va[8] (x * channel_att) survives both barriers. UNCHANGED.
// ---------------------------------------------------------------------------
__global__ void __launch_bounds__(512, 2) fused_kernel(
    const float* __restrict__ x,
    const float* __restrict__ skb,   // [1]
    const float* __restrict__ sks,   // [8]
    float* __restrict__ out)
{
    __shared__ float4 wred[16][TILE_V4];             // 8 KB partial y_spatial
    __shared__ __align__(16) float satts[TILE_VOX];  // per-voxel spatial att

    const int b    = blockIdx.x >> 11;               // TILES_PER_B = 2048
    const int tile = blockIdx.x & (TILES_PER_B - 1);
    const int w    = threadIdx.x >> 5;               // warp 0..15
    const int l    = threadIdx.x & 31;               // float4 lane

    const size_t sbase4 = (size_t)tile * TILE_V4;    // float4 offset in plane
    const float4* xp = (const float4*)x;
    float4* op = (float4*)out;

    float4 va[8];                                     // x * channel_att (regs)
    float4 ws = make_float4(0.f, 0.f, 0.f, 0.f);
    const int cbase = w * 8;
#pragma unroll
    for (int k = 0; k < 8; k++) {
        const int pair = b * C_SZ + cbase + k;
        const float4 v = __ldcs(&xp[((size_t)pair << 16) + sbase4 + (size_t)l]);
        const float a  = g_att[pair];                 // uniform per warp
        const float wc = g_wc[pair];
        va[k] = make_float4(v.x * a, v.y * a, v.z * a, v.w * a);
        ws.x += v.x * wc; ws.y += v.y * wc; ws.z += v.z * wc; ws.w += v.w * wc;
    }
    wred[w][l] = ws;
    __syncthreads();

    // 128 threads: one voxel each — reduce 16 partials, 1->1 KAN spline.
    if (threadIdx.x < TILE_VOX) {
        const int vox = threadIdx.x;
        const int l4  = vox >> 2, j = vox & 3;
        float y = 0.0f;
#pragma unroll
        for (int p = 0; p < 16; p++) y += ((const float*)&wred[p][l4])[j];

        float bas[GBASES];
        bspline8(y, bas);
        float acc = siluf(y) * skb[0];
#pragma unroll
        for (int g = 0; g < GBASES; g++) acc += bas[g] * sks[g];
        satts[vox] = sigmoidf_(acc);
    }
    __syncthreads();

    const float4 sa = ((const float4*)satts)[l];
#pragma unroll
    for (int k = 0; k < 8; k++) {
        const int pair = b * C_SZ + cbase + k;
        __stcs(&op[((size_t)pair << 16) + sbase4 + (size_t)l],
               make_float4(va[k].x * sa.x, va[k].y * sa.y,
                           va[k].z * sa.z, va[k].w * sa.w));
    }
}

// ---------------------------------------------------------------------------
// Launch
// ---------------------------------------------------------------------------
extern "C" void kernel_launch(void* const* d_in, const int* in_sizes, int n_in,
                              void* d_out, int out_size) {
    const float* x     = (const float*)d_in[0];
    const float* ck1b  = (const float*)d_in[1];
    const float* ck1s  = (const float*)d_in[2];
    const float* ck2b  = (const float*)d_in[3];
    const float* ck2s  = (const float*)d_in[4];
    const float* convw = (const float*)d_in[5];
    const float* skb   = (const float*)d_in[6];
    const float* sks   = (const float*)d_in[7];
    float* out = (float*)d_out;

    pool_kernel<<<NPAIR * NCHUNK, 256>>>(x, ck1b, ck1s, ck2b, ck2s, convw);
    att_kernel<<<B_SZ, 256>>>(ck1b, ck1s, ck2b, ck2s, convw);
    fused_kernel<<<B_SZ * TILES_PER_B, 512>>>(x, skb, sks, out);
}

// round 16
// speedup vs baseline: 1.0347x; 1.0347x over previous
#include <cuda_runtime.h>
#include <math.h>

// ---------------------------------------------------------------------------
// Problem constants (shapes fixed by setup_inputs)
// ---------------------------------------------------------------------------
#define B_SZ   2
#define C_SZ   128
#define S_SZ   262144          // 64*64*64 voxels per (b,c)
#define NPAIR  (B_SZ * C_SZ)   // 256
#define NCHUNK 8               // R14 config (NCHUNK=32 regressed; 82% is HBM ceiling)
#define GBASES 8               // GRID_SIZE + SPLINE_ORDER = 5 + 3

#define TILE_VOX 128                   // voxels per fused tile
#define TILE_V4  32                    // float4 lanes per tile
#define TILES_PER_B (S_SZ / TILE_VOX)  // 2048

// Scratch (no device allocation allowed)
__device__ float g_psum[NPAIR * NCHUNK];
__device__ float g_pmax[NPAIR * NCHUNK];
__device__ float g_att[NPAIR];   // sigmoid channel attention per (b,c)
__device__ float g_wc[NPAIR];    // att * conv_w  per (b,c)
__device__ float g_sink;         // prefetch sink (never actually written)

// ---------------------------------------------------------------------------
// Cox-de Boor B-spline bases, k=3, grid = arange(-3,9)*0.4 - 1  (12 knots).
// Uniform grid -> FDIV replaced by multiply with compile-time reciprocals.
// ---------------------------------------------------------------------------
__device__ __forceinline__ void bspline8(float x, float* __restrict__ out) {
    float grid[12];
#pragma unroll
    for (int i = 0; i < 12; i++) grid[i] = (float)(i - 3) * 0.4f - 1.0f;
    float b[11];
#pragma unroll
    for (int j = 0; j < 11; j++)
        b[j] = (x >= grid[j] && x < grid[j + 1]) ? 1.0f : 0.0f;
    const float inv[3] = {2.5f, 1.25f, 1.0f / 1.2f};
#pragma unroll
    for (int j = 1; j <= 3; j++) {
        const float r = inv[j - 1];
#pragma unroll
        for (int m = 0; m < 11; m++) {
            if (m < 11 - j) {
                b[m] = (x - grid[m]) * r * b[m]
                     + (grid[m + j + 1] - x) * r * b[m + 1];
            }
        }
    }
#pragma unroll
    for (int g = 0; g < GBASES; g++) out[g] = b[g];
}

__device__ __forceinline__ float siluf(float v) { return v * (1.0f / (1.0f + __expf(-v))); }
__device__ __forceinline__ float sigmoidf_(float v) { return 1.0f / (1.0f + __expf(-v)); }

// ---------------------------------------------------------------------------
// Kernel 1: per-(b,c) partial sum/max pooling (PROVEN ~41-43us, HBM ceiling).
// Block 0 pre-touches the 41 KB of MLP weights into L2 for the att kernel.
// ---------------------------------------------------------------------------
__global__ void __launch_bounds__(256) pool_kernel(
    const float* __restrict__ x,
    const float* __restrict__ ck1b, const float* __restrict__ ck1s,
    const float* __restrict__ ck2b, const float* __restrict__ ck2s,
    const float* __restrict__ convw)
{
    if (blockIdx.x == 0) {
        float acc = 0.0f;
        for (int i = threadIdx.x; i < 8192; i += 256)
            acc += __ldcg(&ck1s[i]) + __ldcg(&ck2s[i]);
        for (int i = threadIdx.x; i < 1024; i += 256)
            acc += __ldcg(&ck1b[i]) + __ldcg(&ck2b[i]);
        if (threadIdx.x < 128) acc += __ldcg(&convw[threadIdx.x]);
        if (acc == 123456789.0f) g_sink = acc;  // keep loads alive; never true
    }

    const int pair  = blockIdx.x >> 3;
    const int chunk = blockIdx.x & 7;
    const float4* p = (const float4*)(x + (size_t)pair * S_SZ + (size_t)chunk * (S_SZ / NCHUNK));

    float s = 0.0f, m = -3.4e38f;
#pragma unroll 4
    for (int it = 0; it < (S_SZ / NCHUNK / 4) / 256; it++) {
        float4 v = __ldcs(&p[it * 256 + threadIdx.x]);
        s += (v.x + v.y) + (v.z + v.w);
        m = fmaxf(m, fmaxf(fmaxf(v.x, v.y), fmaxf(v.z, v.w)));
    }
#pragma unroll
    for (int o = 16; o; o >>= 1) {
        s += __shfl_xor_sync(0xffffffffu, s, o);
        m = fmaxf(m, __shfl_xor_sync(0xffffffffu, m, o));
    }
    __shared__ float ss[8], sm[8];
    const int w = threadIdx.x >> 5, l = threadIdx.x & 31;
    if (l == 0) { ss[w] = s; sm[w] = m; }
    __syncthreads();
    if (threadIdx.x == 0) {
        float ts = 0.0f, tm = -3.4e38f;
#pragma unroll
        for (int i = 0; i < 8; i++) { ts += ss[i]; tm = fmaxf(tm, sm[i]); }
        g_psum[blockIdx.x] = ts;
        g_pmax[blockIdx.x] = tm;
    }
}

// ---------------------------------------------------------------------------
// Kernel 2: channel attention MLP — TWO blocks, one per batch (PROVEN R14).
// PDL: launched programmatically; gridDepSync before reading pool results.
// ---------------------------------------------------------------------------
__global__ void __launch_bounds__(256) att_kernel(
    const float* __restrict__ ck1b,   // [8,128]
    const float* __restrict__ ck1s,   // [8,128,8]
    const float* __restrict__ ck2b,   // [128,8]
    const float* __restrict__ ck2s,   // [128,8,8]
    const float* __restrict__ convw)  // [128]
{
    __shared__ float s_silu[256];           // [src(2)][c(128)]
    __shared__ float s_bas[256][GBASES];
    __shared__ float s_h1silu[16];          // [src][r]
    __shared__ float s_h1bas[16][GBASES];
    __shared__ float s_out[256];            // [src][c]

    const int b   = blockIdx.x;             // batch
    const int tid = threadIdx.x;

    cudaGridDependencySynchronize();        // wait for pool's g_psum/g_pmax

    // phase 0+1: each thread reduces one pooled value (src,c), silu + bases.
    {
        const int src = tid >> 7;            // 0 = avg, 1 = max
        const int c   = tid & 127;
        const int pair = b * C_SZ + c;
        float v;
        if (src == 0) {
            float ts = 0.0f;
#pragma unroll
            for (int k = 0; k < NCHUNK; k++) ts += g_psum[pair * NCHUNK + k];
            v = ts * (1.0f / (float)S_SZ);
        } else {
            float tm = -3.4e38f;
#pragma unroll
            for (int k = 0; k < NCHUNK; k++) tm = fmaxf(tm, g_pmax[pair * NCHUNK + k]);
            v = tm;
        }
        s_silu[tid] = siluf(v);
        bspline8(v, s_bas[tid]);
    }
    __syncthreads();

    // phase 2: layer 1 -> h1. 16 tasks (src x r) x 16 lanes (8 channels each).
    {
        const int task = tid >> 4;            // 0..15
        const int j    = tid & 15;
        const int src  = task >> 3, r = task & 7;
        const int base = src * 128;
        float acc = 0.0f;
#pragma unroll
        for (int ii = 0; ii < 8; ii++) {
            const int i = j + ii * 16;
            const int q = base + i;
            acc += s_silu[q] * ck1b[r * C_SZ + i];
            const float4* sw = (const float4*)(ck1s + (r * C_SZ + i) * GBASES);
            const float4 a0 = sw[0], a1 = sw[1];
            acc += s_bas[q][0] * a0.x + s_bas[q][1] * a0.y
                 + s_bas[q][2] * a0.z + s_bas[q][3] * a0.w
                 + s_bas[q][4] * a1.x + s_bas[q][5] * a1.y
                 + s_bas[q][6] * a1.z + s_bas[q][7] * a1.w;
        }
#pragma unroll
        for (int o = 8; o; o >>= 1) acc += __shfl_xor_sync(0xffffffffu, acc, o);
        if (j == 0) {
            const float hv = fmaxf(acc, 0.0f);
            s_h1silu[task] = siluf(hv);        // task = src*8 + r
            bspline8(hv, s_h1bas[task]);
        }
    }
    __syncthreads();

    // phase 3: layer 2 — one (src,c) output per thread.
    {
        const int src = tid >> 7, c = tid & 127;
        float acc = 0.0f;
#pragma unroll
        for (int r = 0; r < 8; r++) {
            const int hq = src * 8 + r;
            acc += s_h1silu[hq] * ck2b[c * 8 + r];
            const float4* sw = (const float4*)(ck2s + (c * 8 + r) * GBASES);
            const float4 a0 = sw[0], a1 = sw[1];
            acc += s_h1bas[hq][0] * a0.x + s_h1bas[hq][1] * a0.y
                 + s_h1bas[hq][2] * a0.z + s_h1bas[hq][3] * a0.w
                 + s_h1bas[hq][4] * a1.x + s_h1bas[hq][5] * a1.y
                 + s_h1bas[hq][6] * a1.z + s_h1bas[hq][7] * a1.w;
        }
        s_out[tid] = acc;
    }
    __syncthreads();

    // phase 4: combine avg+max, sigmoid, fold in conv_w.
    if (tid < 128) {
        const float a = sigmoidf_(s_out[tid] + s_out[128 + tid]);
        g_att[b * C_SZ + tid] = a;
        g_wc[b * C_SZ + tid]  = a * convw[tid];
    }
}

// ---------------------------------------------------------------------------
// Kernel 3: fused spatial pass — WARP-CONTIGUOUS 512B segments (PROVEN ~79us,
// mixed R/W roofline). PDL: launches while att runs; issues its independent
// raw x loads FIRST, then gridDepSync, then reads g_att/g_wc.
// ---------------------------------------------------------------------------
__global__ void __launch_bounds__(512, 2) fused_kernel(
    const float* __restrict__ x,
    const float* __restrict__ skb,   // [1]
    const float* __restrict__ sks,   // [8]
    float* __restrict__ out)
{
    __shared__ float4 wred[16][TILE_V4];             // 8 KB partial y_spatial
    __shared__ __align__(16) float satts[TILE_VOX];  // per-voxel spatial att

    const int b    = blockIdx.x >> 11;               // TILES_PER_B = 2048
    const int tile = blockIdx.x & (TILES_PER_B - 1);
    const int w    = threadIdx.x >> 5;               // warp 0..15
    const int l    = threadIdx.x & 31;               // float4 lane

    const size_t sbase4 = (size_t)tile * TILE_V4;    // float4 offset in plane
    const float4* xp = (const float4*)x;
    float4* op = (float4*)out;

    // Raw x loads first — independent of the attention values (overlaps att).
    float4 va[8];
    const int cbase = w * 8;
#pragma unroll
    for (int k = 0; k < 8; k++) {
        const int pair = b * C_SZ + cbase + k;
        va[k] = __ldcs(&xp[((size_t)pair << 16) + sbase4 + (size_t)l]);
    }

    cudaGridDependencySynchronize();                  // wait for att's g_att/g_wc

    // Scale by channel attention; accumulate spatial partial sums.
    float4 ws = make_float4(0.f, 0.f, 0.f, 0.f);
#pragma unroll
    for (int k = 0; k < 8; k++) {
        const int pair = b * C_SZ + cbase + k;
        const float a  = g_att[pair];                 // uniform per warp, L1-cached
        const float wc = g_wc[pair];
        ws.x += va[k].x * wc; ws.y += va[k].y * wc;
        ws.z += va[k].z * wc; ws.w += va[k].w * wc;
        va[k].x *= a; va[k].y *= a; va[k].z *= a; va[k].w *= a;
    }
    wred[w][l] = ws;
    __syncthreads();

    // 128 threads: one voxel each — reduce 16 partials, 1->1 KAN spline.
    if (threadIdx.x < TILE_VOX) {
        const int vox = threadIdx.x;
        const int l4  = vox >> 2, j = vox & 3;
        float y = 0.0f;
#pragma unroll
        for (int p = 0; p < 16; p++) y += ((const float*)&wred[p][l4])[j];

        float bas[GBASES];
        bspline8(y, bas);
        float acc = siluf(y) * skb[0];
#pragma unroll
        for (int g = 0; g < GBASES; g++) acc += bas[g] * sks[g];
        satts[vox] = sigmoidf_(acc);
    }
    __syncthreads();

    const float4 sa = ((const float4*)satts)[l];
#pragma unroll
    for (int k = 0; k < 8; k++) {
        const int pair = b * C_SZ + cbase + k;
        __stcs(&op[((size_t)pair << 16) + sbase4 + (size_t)l],
               make_float4(va[k].x * sa.x, va[k].y * sa.y,
                           va[k].z * sa.z, va[k].w * sa.w));
    }
}

// ---------------------------------------------------------------------------
// Launch — att and fused use programmatic dependent launch to overlap the
// predecessor's drain with their own ramp-up. gridDepSync preserves ordering.
// ---------------------------------------------------------------------------
extern "C" void kernel_launch(void* const* d_in, const int* in_sizes, int n_in,
                              void* d_out, int out_size) {
    const float* x     = (const float*)d_in[0];
    const float* ck1b  = (const float*)d_in[1];
    const float* ck1s  = (const float*)d_in[2];
    const float* ck2b  = (const float*)d_in[3];
    const float* ck2s  = (const float*)d_in[4];
    const float* convw = (const float*)d_in[5];
    const float* skb   = (const float*)d_in[6];
    const float* sks   = (const float*)d_in[7];
    float* out = (float*)d_out;

    pool_kernel<<<NPAIR * NCHUNK, 256>>>(x, ck1b, ck1s, ck2b, ck2s, convw);

    cudaLaunchAttribute attr[1];
    attr[0].id = cudaLaunchAttributeProgrammaticStreamSerialization;
    attr[0].val.programmaticStreamSerializationAllowed = 1;

    {
        cudaLaunchConfig_t cfg = {};
        cfg.gridDim  = dim3(B_SZ, 1, 1);
        cfg.blockDim = dim3(256, 1, 1);
        cfg.attrs    = attr;
        cfg.numAttrs = 1;
        cudaLaunchKernelEx(&cfg, att_kernel, ck1b, ck1s, ck2b, ck2s, convw);
    }
    {
        cudaLaunchConfig_t cfg = {};
        cfg.gridDim  = dim3(B_SZ * TILES_PER_B, 1, 1);
        cfg.blockDim = dim3(512, 1, 1);
        cfg.attrs    = attr;
        cfg.numAttrs = 1;
        cudaLaunchKernelEx(&cfg, fused_kernel, x, skb, sks, out);
    }
}